// round 1
// baseline (speedup 1.0000x reference)
#include <cuda_runtime.h>
#include <math.h>

// ---------------------------------------------------------------------------
// FrameTransformer: B=1, C=8, F=1024, W=512, H=16, D=64, EXP=4
// Round 1: all-fp32 correctness baseline with tiled SGEMMs.
// ---------------------------------------------------------------------------

#define CC 8
#define FF 1024
#define WW 512
#define HH 16
#define DD 64
#define EXPAND 4
#define FHID (FF * EXPAND)   // 4096
#define NELEM (CC * FF * WW) // 4,194,304

// Scratch (device globals; no runtime allocation allowed)
__device__ float g_z[NELEM];                 // LN output
__device__ float g_p[NELEM];                 // P = Wq @ z  (also V)
__device__ float g_q[NELEM];                 // RoPE(P) (q == k)
__device__ float g_s[CC * HH * WW * WW];     // attention scores / probs (134 MB)
__device__ float g_o[NELEM];                 // attention output (pre-Wo)
__device__ float g_h[CC * FHID * WW];        // MLP hidden (67 MB)

// ---------------------------------------------------------------------------
// Frame norm over F for each (c, w) column. x layout: [C][F][W]
// block = (32 w, 8 f-strips); grid = (W/32, C)
// ---------------------------------------------------------------------------
__global__ void ln_kernel(const float* __restrict__ x,
                          const float* __restrict__ g,
                          const float* __restrict__ b,
                          float* __restrict__ z)
{
    const int c  = blockIdx.y;
    const int w  = blockIdx.x * 32 + threadIdx.x;
    const int ty = threadIdx.y;
    const float* xc = x + (size_t)c * FF * WW;
    float*       zc = z + (size_t)c * FF * WW;

    float sum = 0.f, sq = 0.f;
    for (int f = ty; f < FF; f += 8) {
        float v = xc[(size_t)f * WW + w];
        sum += v;
        sq  = fmaf(v, v, sq);
    }
    __shared__ float s_sum[8][32];
    __shared__ float s_sq[8][32];
    s_sum[ty][threadIdx.x] = sum;
    s_sq[ty][threadIdx.x]  = sq;
    __syncthreads();
    if (ty == 0) {
        #pragma unroll
        for (int i = 1; i < 8; ++i) {
            sum += s_sum[i][threadIdx.x];
            sq  += s_sq[i][threadIdx.x];
        }
        float mu  = sum * (1.0f / FF);
        float var = sq * (1.0f / FF) - mu * mu;
        s_sum[0][threadIdx.x] = mu;
        s_sq[0][threadIdx.x]  = rsqrtf(var + 1e-5f);
    }
    __syncthreads();
    const float mu   = s_sum[0][threadIdx.x];
    const float rinv = s_sq[0][threadIdx.x];
    for (int f = ty; f < FF; f += 8) {
        float v = xc[(size_t)f * WW + w];
        zc[(size_t)f * WW + w] = (v - mu) * rinv * g[f] + b[f];
    }
}

// ---------------------------------------------------------------------------
// Batched SGEMM: Out[c] = W[c] (MxK, row-major) @ In[c] (KxN=512, row-major)
// MODE 0: store; 1: store + Res; 2: store gelu(acc); 3: Out += acc
// block = 256 threads, 128x128 tile, 8x8 per thread, BK=8
// Requires M % 128 == 0, K % 8 == 0, N == 512.
// ---------------------------------------------------------------------------
template <int MODE>
__global__ __launch_bounds__(256)
void sgemm_kernel(const float* __restrict__ Wt, const float* __restrict__ In,
                  float* __restrict__ Out, const float* __restrict__ Res,
                  int M, int K)
{
    const int c = blockIdx.z;
    Wt += (size_t)c * M * K;
    In += (size_t)c * K * WW;
    Out += (size_t)c * M * WW;
    if (MODE == 1) Res += (size_t)c * M * WW;

    __shared__ float As[8][128];
    __shared__ float Bs[8][128];

    const int tid = threadIdx.x;
    const int m0  = blockIdx.y * 128;
    const int n0  = blockIdx.x * 128;
    const int tx  = tid & 15;
    const int ty  = tid >> 4;

    const int a_row = tid >> 1;
    const int a_col = (tid & 1) * 4;
    const int b_row = tid >> 5;
    const int b_col = (tid & 31) * 4;

    const float* Ap = Wt + (size_t)(m0 + a_row) * K + a_col;
    const float* Bp = In + (size_t)b_row * WW + n0 + b_col;

    float acc[8][8];
    #pragma unroll
    for (int i = 0; i < 8; ++i)
        #pragma unroll
        for (int j = 0; j < 8; ++j) acc[i][j] = 0.f;

    for (int k0 = 0; k0 < K; k0 += 8) {
        float4 av = *(const float4*)(Ap + k0);
        float4 bv = *(const float4*)(Bp + (size_t)k0 * WW);
        As[a_col + 0][a_row] = av.x;
        As[a_col + 1][a_row] = av.y;
        As[a_col + 2][a_row] = av.z;
        As[a_col + 3][a_row] = av.w;
        *(float4*)&Bs[b_row][b_col] = bv;
        __syncthreads();
        #pragma unroll
        for (int kk = 0; kk < 8; ++kk) {
            float a0[8], b0[8];
            #pragma unroll
            for (int i = 0; i < 8; ++i) a0[i] = As[kk][ty * 8 + i];
            #pragma unroll
            for (int j = 0; j < 8; ++j) b0[j] = Bs[kk][tx * 8 + j];
            #pragma unroll
            for (int i = 0; i < 8; ++i)
                #pragma unroll
                for (int j = 0; j < 8; ++j)
                    acc[i][j] = fmaf(a0[i], b0[j], acc[i][j]);
        }
        __syncthreads();
    }

    #pragma unroll
    for (int i = 0; i < 8; ++i) {
        const int row = m0 + ty * 8 + i;
        const size_t base = (size_t)row * WW + n0 + tx * 8;
        #pragma unroll
        for (int j = 0; j < 8; ++j) {
            float v = acc[i][j];
            if (MODE == 1) v += Res[base + j];
            else if (MODE == 2) v = 0.5f * v * (1.0f + erff(v * 0.70710678118654752f));
            else if (MODE == 3) v += Out[base + j];
            Out[base + j] = v;
        }
    }
}

// ---------------------------------------------------------------------------
// RoPE: q[c, h*64+d, w].  First 32 dims of each head rotated (interleaved).
// ---------------------------------------------------------------------------
__global__ void rope_kernel(const float* __restrict__ p,
                            const float* __restrict__ freqs,
                            float* __restrict__ q)
{
    int n = blockIdx.x * blockDim.x + threadIdx.x;
    if (n >= NELEM) return;
    const int w = n & (WW - 1);
    const int f = (n >> 9) & (FF - 1);
    const int d = f & (DD - 1);
    float v = p[n];
    if (d >= 32) { q[n] = v; return; }
    const int j = d >> 1;
    const float ang = (float)w * freqs[j];
    const float cs = cosf(ang);
    const float sn = sinf(ang);
    if ((d & 1) == 0) {
        float v2 = p[n + WW];           // partner f+1
        q[n] = v * cs - v2 * sn;
    } else {
        float v2 = p[n - WW];           // partner f-1
        q[n] = v * cs + v2 * sn;
    }
}

// ---------------------------------------------------------------------------
// Scores: per (c,h): S[q,k] = (1/32) * sum_d Q[d,q]*Q[d,k]  (q == k matrix)
// Q slab layout [d(64)][w(512)] with row stride 512.
// grid = (8 ktile, 8 qtile, 128 heads), block = 256, 4x4 per thread, full K=64.
// ---------------------------------------------------------------------------
__global__ __launch_bounds__(256)
void scores_kernel(const float* __restrict__ Qg, float* __restrict__ S)
{
    const int ch = blockIdx.z;
    const float* Q = Qg + (size_t)((ch >> 4) * FF + (ch & 15) * DD) * WW;
    const int q0 = blockIdx.y * 64;
    const int k0 = blockIdx.x * 64;

    __shared__ float Aq[64][65];
    __shared__ float Ak[64][65];
    const int tid = threadIdx.x;
    for (int i = tid; i < 64 * 64; i += 256) {
        const int d = i >> 6, pos = i & 63;
        Aq[d][pos] = Q[(size_t)d * WW + q0 + pos];
        Ak[d][pos] = Q[(size_t)d * WW + k0 + pos];
    }
    __syncthreads();

    const int tx = tid & 15, ty = tid >> 4;
    float acc[4][4];
    #pragma unroll
    for (int i = 0; i < 4; ++i)
        #pragma unroll
        for (int j = 0; j < 4; ++j) acc[i][j] = 0.f;

    #pragma unroll 8
    for (int d = 0; d < 64; ++d) {
        float aq[4], ak[4];
        #pragma unroll
        for (int i = 0; i < 4; ++i) aq[i] = Aq[d][ty * 4 + i];
        #pragma unroll
        for (int j = 0; j < 4; ++j) ak[j] = Ak[d][tx * 4 + j];
        #pragma unroll
        for (int i = 0; i < 4; ++i)
            #pragma unroll
            for (int j = 0; j < 4; ++j)
                acc[i][j] = fmaf(aq[i], ak[j], acc[i][j]);
    }

    float* Sb = S + (size_t)ch * WW * WW;
    const float scale = 1.0f / 32.0f;   // 1/sqrt(F)
    #pragma unroll
    for (int i = 0; i < 4; ++i)
        #pragma unroll
        for (int j = 0; j < 4; ++j)
            Sb[(size_t)(q0 + ty * 4 + i) * WW + k0 + tx * 4 + j] = acc[i][j] * scale;
}

// ---------------------------------------------------------------------------
// Row softmax over 512 elements; one warp per row.
// ---------------------------------------------------------------------------
__global__ void softmax_kernel(float* __restrict__ S)
{
    const int row  = blockIdx.x * 8 + (threadIdx.x >> 5);
    const int lane = threadIdx.x & 31;
    float* Sr = S + (size_t)row * WW;

    float v[16];
    float mx = -1e30f;
    #pragma unroll
    for (int i = 0; i < 16; ++i) {
        v[i] = Sr[lane + i * 32];
        mx = fmaxf(mx, v[i]);
    }
    #pragma unroll
    for (int o = 16; o > 0; o >>= 1) mx = fmaxf(mx, __shfl_xor_sync(0xFFFFFFFFu, mx, o));
    float sum = 0.f;
    #pragma unroll
    for (int i = 0; i < 16; ++i) {
        v[i] = expf(v[i] - mx);
        sum += v[i];
    }
    #pragma unroll
    for (int o = 16; o > 0; o >>= 1) sum += __shfl_xor_sync(0xFFFFFFFFu, sum, o);
    const float inv = 1.0f / sum;
    #pragma unroll
    for (int i = 0; i < 16; ++i) Sr[lane + i * 32] = v[i] * inv;
}

// ---------------------------------------------------------------------------
// O[d,q] = sum_k V[d,k] * A[q,k]  per head.  M=64(d), N=512(q), K=512.
// grid = (8 qtiles, 128 heads), block = 256, 4x4 per thread, BK=32.
// ---------------------------------------------------------------------------
__global__ __launch_bounds__(256)
void av_kernel(const float* __restrict__ S, const float* __restrict__ Vg,
               float* __restrict__ Og)
{
    const int ch = blockIdx.y;
    const size_t hoff = (size_t)((ch >> 4) * FF + (ch & 15) * DD) * WW;
    const float* V = Vg + hoff;
    float*       O = Og + hoff;
    const float* A = S + (size_t)ch * WW * WW;
    const int q0 = blockIdx.x * 64;

    __shared__ float Vs[64][33];
    __shared__ float As[64][33];
    const int tid = threadIdx.x;
    const int tx = tid & 15, ty = tid >> 4;

    float acc[4][4];
    #pragma unroll
    for (int i = 0; i < 4; ++i)
        #pragma unroll
        for (int j = 0; j < 4; ++j) acc[i][j] = 0.f;

    for (int k0 = 0; k0 < WW; k0 += 32) {
        for (int i = tid; i < 64 * 32; i += 256) {
            const int r = i >> 5, k = i & 31;
            Vs[r][k] = V[(size_t)r * WW + k0 + k];
            As[r][k] = A[(size_t)(q0 + r) * WW + k0 + k];
        }
        __syncthreads();
        #pragma unroll 8
        for (int k = 0; k < 32; ++k) {
            float vf[4], af[4];
            #pragma unroll
            for (int i = 0; i < 4; ++i) vf[i] = Vs[ty * 4 + i][k];
            #pragma unroll
            for (int j = 0; j < 4; ++j) af[j] = As[tx * 4 + j][k];
            #pragma unroll
            for (int i = 0; i < 4; ++i)
                #pragma unroll
                for (int j = 0; j < 4; ++j)
                    acc[i][j] = fmaf(vf[i], af[j], acc[i][j]);
        }
        __syncthreads();
    }
    #pragma unroll
    for (int i = 0; i < 4; ++i)
        #pragma unroll
        for (int j = 0; j < 4; ++j)
            O[(size_t)(ty * 4 + i) * WW + q0 + tx * 4 + j] = acc[i][j];
}

// ---------------------------------------------------------------------------
// Launch
// ---------------------------------------------------------------------------
extern "C" void kernel_launch(void* const* d_in, const int* in_sizes, int n_in,
                              void* d_out, int out_size)
{
    const float* x   = (const float*)d_in[0];
    const float* n1g = (const float*)d_in[1];
    const float* n1b = (const float*)d_in[2];
    const float* wq  = (const float*)d_in[3];
    const float* wo  = (const float*)d_in[4];
    const float* rf  = (const float*)d_in[5];
    const float* n2g = (const float*)d_in[6];
    const float* n2b = (const float*)d_in[7];
    const float* w1  = (const float*)d_in[8];
    const float* w2  = (const float*)d_in[9];
    float* out = (float*)d_out;

    float *z, *p, *q, *s, *o, *h;
    cudaGetSymbolAddress((void**)&z, g_z);
    cudaGetSymbolAddress((void**)&p, g_p);
    cudaGetSymbolAddress((void**)&q, g_q);
    cudaGetSymbolAddress((void**)&s, g_s);
    cudaGetSymbolAddress((void**)&o, g_o);
    cudaGetSymbolAddress((void**)&h, g_h);

    dim3 lnBlock(32, 8), lnGrid(WW / 32, CC);

    // 1. z = LN1(x)
    ln_kernel<<<lnGrid, lnBlock>>>(x, n1g, n1b, z);
    // 2. p = Wq @ z
    sgemm_kernel<0><<<dim3(4, 8, CC), 256>>>(wq, z, p, nullptr, FF, FF);
    // 3. q = rope(p)
    rope_kernel<<<NELEM / 256, 256>>>(p, rf, q);
    // 4. scores
    scores_kernel<<<dim3(8, 8, CC * HH), 256>>>(q, s);
    // 5. softmax
    softmax_kernel<<<CC * HH * WW / 8, 256>>>(s);
    // 6. o = A @ V   (V = p)
    av_kernel<<<dim3(8, CC * HH), 256>>>(s, p, o);
    // 7. out = x + Wo @ o
    sgemm_kernel<1><<<dim3(4, 8, CC), 256>>>(wo, o, out, x, FF, FF);
    // 8. z = LN2(out)
    ln_kernel<<<lnGrid, lnBlock>>>(out, n2g, n2b, z);
    // 9. h = gelu(W1 @ z)
    sgemm_kernel<2><<<dim3(4, FHID / 128, CC), 256>>>(w1, z, h, nullptr, FHID, FF);
    // 10. out += W2 @ h
    sgemm_kernel<3><<<dim3(4, 8, CC), 256>>>(w2, h, out, nullptr, FF, FHID);
}

// round 3
// speedup vs baseline: 2.1706x; 2.1706x over previous
#include <cuda_runtime.h>
#include <math.h>
#include <stdint.h>

// ---------------------------------------------------------------------------
// FrameTransformer: B=1, C=8, F=1024, W=512, H=16, D=64, EXP=4
// Round 3: all GEMMs on tensor cores via mma.sync m16n8k8 tf32 (fp32 accum).
// ---------------------------------------------------------------------------

#define CC 8
#define FF 1024
#define WW 512
#define HH 16
#define DD 64
#define EXPAND 4
#define FHID (FF * EXPAND)   // 4096
#define NELEM (CC * FF * WW) // 4,194,304

// Scratch (device globals; no runtime allocation allowed)
__device__ float g_z[NELEM];                 // LN output
__device__ float g_p[NELEM];                 // P = Wq @ z  (also V)
__device__ float g_q[NELEM];                 // RoPE(P) (q == k)
__device__ float g_s[CC * HH * WW * WW];     // attention scores / probs (134 MB)
__device__ float g_o[NELEM];                 // attention output (pre-Wo)
__device__ float g_h[CC * FHID * WW];        // MLP hidden (67 MB)

__device__ __forceinline__ float to_tf32(float x) {
    uint32_t u;
    asm("cvt.rna.tf32.f32 %0, %1;" : "=r"(u) : "f"(x));
    return __uint_as_float(u);
}

#define MMA_TF32(C, A, B)                                                     \
    asm volatile(                                                             \
        "mma.sync.aligned.m16n8k8.row.col.f32.tf32.tf32.f32 "                 \
        "{%0,%1,%2,%3}, {%4,%5,%6,%7}, {%8,%9}, {%0,%1,%2,%3};"               \
        : "+f"((C)[0]), "+f"((C)[1]), "+f"((C)[2]), "+f"((C)[3])              \
        : "r"((A)[0]), "r"((A)[1]), "r"((A)[2]), "r"((A)[3]),                 \
          "r"((B)[0]), "r"((B)[1]))

// ---------------------------------------------------------------------------
// Frame norm over F for each (c, w) column. x layout: [C][F][W]
// ---------------------------------------------------------------------------
__global__ void ln_kernel(const float* __restrict__ x,
                          const float* __restrict__ g,
                          const float* __restrict__ b,
                          float* __restrict__ z)
{
    const int c  = blockIdx.y;
    const int w  = blockIdx.x * 32 + threadIdx.x;
    const int ty = threadIdx.y;
    const float* xc = x + (size_t)c * FF * WW;
    float*       zc = z + (size_t)c * FF * WW;

    float sum = 0.f, sq = 0.f;
    for (int f = ty; f < FF; f += 8) {
        float v = xc[(size_t)f * WW + w];
        sum += v;
        sq  = fmaf(v, v, sq);
    }
    __shared__ float s_sum[8][32];
    __shared__ float s_sq[8][32];
    s_sum[ty][threadIdx.x] = sum;
    s_sq[ty][threadIdx.x]  = sq;
    __syncthreads();
    if (ty == 0) {
        #pragma unroll
        for (int i = 1; i < 8; ++i) {
            sum += s_sum[i][threadIdx.x];
            sq  += s_sq[i][threadIdx.x];
        }
        float mu  = sum * (1.0f / FF);
        float var = sq * (1.0f / FF) - mu * mu;
        s_sum[0][threadIdx.x] = mu;
        s_sq[0][threadIdx.x]  = rsqrtf(var + 1e-5f);
    }
    __syncthreads();
    const float mu   = s_sum[0][threadIdx.x];
    const float rinv = s_sq[0][threadIdx.x];
    for (int f = ty; f < FF; f += 8) {
        float v = xc[(size_t)f * WW + w];
        zc[(size_t)f * WW + w] = (v - mu) * rinv * g[f] + b[f];
    }
}

// ---------------------------------------------------------------------------
// Tensor-core batched GEMM: Out[c] = W[c] (MxK row-major) @ In[c] (Kx512 rm)
// MODE 0: store; 1: store + Res; 2: store gelu(acc); 3: Out += acc
// block = 256 thr (8 warps), tile 128x128, warp 64x32, KB=16, tf32 mma.
// ---------------------------------------------------------------------------
template <int MODE>
__global__ __launch_bounds__(256)
void tgemm_kernel(const float* __restrict__ Wt, const float* __restrict__ In,
                  float* __restrict__ Out, const float* __restrict__ Res,
                  int M, int K)
{
    const int c = blockIdx.z;
    Wt  += (size_t)c * M * K;
    In  += (size_t)c * K * WW;
    Out += (size_t)c * M * WW;
    if (MODE == 1) Res += (size_t)c * M * WW;

    __shared__ float As[16][132];   // [k][m]
    __shared__ float Bs[16][132];   // [k][n]

    const int tid  = threadIdx.x;
    const int lane = tid & 31;
    const int wid  = tid >> 5;
    const int m0   = blockIdx.y * 128;
    const int n0   = blockIdx.x * 128;
    const int wm   = (wid >> 2) * 64;
    const int wn   = (wid & 3) * 32;
    const int lg   = lane >> 2;     // group id 0..7
    const int lt   = lane & 3;      // thread-in-group

    // global load mapping
    const int ar = tid >> 1;              // 0..127 (m row)
    const int ac = (tid & 1) * 8;         // k col base
    const int br = tid >> 5;              // 0..7   (k row)
    const int bc = (tid & 31) * 4;        // n col base

    const float* Ap = Wt + (size_t)(m0 + ar) * K + ac;
    const float* Bp = In + n0 + bc;

    float4 pa0, pa1, pb0, pb1;
    pa0 = *(const float4*)(Ap);
    pa1 = *(const float4*)(Ap + 4);
    pb0 = *(const float4*)(Bp + (size_t)br * WW);
    pb1 = *(const float4*)(Bp + (size_t)(br + 8) * WW);

    float acc[4][4][4];
    #pragma unroll
    for (int mi = 0; mi < 4; ++mi)
        #pragma unroll
        for (int ni = 0; ni < 4; ++ni)
            #pragma unroll
            for (int r = 0; r < 4; ++r) acc[mi][ni][r] = 0.f;

    for (int k0 = 0; k0 < K; k0 += 16) {
        // stage current regs -> smem (tf32-rounded)
        As[ac + 0][ar] = to_tf32(pa0.x);
        As[ac + 1][ar] = to_tf32(pa0.y);
        As[ac + 2][ar] = to_tf32(pa0.z);
        As[ac + 3][ar] = to_tf32(pa0.w);
        As[ac + 4][ar] = to_tf32(pa1.x);
        As[ac + 5][ar] = to_tf32(pa1.y);
        As[ac + 6][ar] = to_tf32(pa1.z);
        As[ac + 7][ar] = to_tf32(pa1.w);
        Bs[br][bc + 0]     = to_tf32(pb0.x);
        Bs[br][bc + 1]     = to_tf32(pb0.y);
        Bs[br][bc + 2]     = to_tf32(pb0.z);
        Bs[br][bc + 3]     = to_tf32(pb0.w);
        Bs[br + 8][bc + 0] = to_tf32(pb1.x);
        Bs[br + 8][bc + 1] = to_tf32(pb1.y);
        Bs[br + 8][bc + 2] = to_tf32(pb1.z);
        Bs[br + 8][bc + 3] = to_tf32(pb1.w);
        __syncthreads();

        if (k0 + 16 < K) {
            pa0 = *(const float4*)(Ap + k0 + 16);
            pa1 = *(const float4*)(Ap + k0 + 20);
            pb0 = *(const float4*)(Bp + (size_t)(k0 + 16 + br) * WW);
            pb1 = *(const float4*)(Bp + (size_t)(k0 + 24 + br) * WW);
        }

        #pragma unroll
        for (int ks = 0; ks < 2; ++ks) {
            const int kb = ks * 8 + lt;
            uint32_t a[4][4];
            #pragma unroll
            for (int mi = 0; mi < 4; ++mi) {
                const int m = wm + mi * 16 + lg;
                a[mi][0] = __float_as_uint(As[kb][m]);
                a[mi][1] = __float_as_uint(As[kb][m + 8]);
                a[mi][2] = __float_as_uint(As[kb + 4][m]);
                a[mi][3] = __float_as_uint(As[kb + 4][m + 8]);
            }
            uint32_t bf[4][2];
            #pragma unroll
            for (int ni = 0; ni < 4; ++ni) {
                const int n = wn + ni * 8 + lg;
                bf[ni][0] = __float_as_uint(Bs[kb][n]);
                bf[ni][1] = __float_as_uint(Bs[kb + 4][n]);
            }
            #pragma unroll
            for (int mi = 0; mi < 4; ++mi)
                #pragma unroll
                for (int ni = 0; ni < 4; ++ni)
                    MMA_TF32(acc[mi][ni], a[mi], bf[ni]);
        }
        __syncthreads();
    }

    // epilogue
    #pragma unroll
    for (int mi = 0; mi < 4; ++mi) {
        const int r0 = m0 + wm + mi * 16 + lg;
        #pragma unroll
        for (int ni = 0; ni < 4; ++ni) {
            const int cc = n0 + wn + ni * 8 + lt * 2;
            #pragma unroll
            for (int half = 0; half < 2; ++half) {
                const int row = r0 + half * 8;
                const size_t idx = (size_t)row * WW + cc;
                float v0 = acc[mi][ni][half * 2 + 0];
                float v1 = acc[mi][ni][half * 2 + 1];
                if (MODE == 1) {
                    float2 rv = *(const float2*)(Res + idx);
                    v0 += rv.x; v1 += rv.y;
                } else if (MODE == 2) {
                    v0 = 0.5f * v0 * (1.0f + erff(v0 * 0.70710678118654752f));
                    v1 = 0.5f * v1 * (1.0f + erff(v1 * 0.70710678118654752f));
                } else if (MODE == 3) {
                    float2 rv = *(const float2*)(Out + idx);
                    v0 += rv.x; v1 += rv.y;
                }
                *(float2*)(Out + idx) = make_float2(v0, v1);
            }
        }
    }
}

// ---------------------------------------------------------------------------
// RoPE: q[c, h*64+d, w]. First 32 dims of each head rotated (interleaved).
// ---------------------------------------------------------------------------
__global__ void rope_kernel(const float* __restrict__ p,
                            const float* __restrict__ freqs,
                            float* __restrict__ q)
{
    int n = blockIdx.x * blockDim.x + threadIdx.x;
    if (n >= NELEM) return;
    const int w = n & (WW - 1);
    const int f = (n >> 9) & (FF - 1);
    const int d = f & (DD - 1);
    float v = p[n];
    if (d >= 32) { q[n] = v; return; }
    const int j = d >> 1;
    const float ang = (float)w * freqs[j];
    const float cs = cosf(ang);
    const float sn = sinf(ang);
    if ((d & 1) == 0) {
        float v2 = p[n + WW];
        q[n] = v * cs - v2 * sn;
    } else {
        float v2 = p[n - WW];
        q[n] = v * cs + v2 * sn;
    }
}

// ---------------------------------------------------------------------------
// Scores (tensor core): per (c,h): S[q,k] = (1/32) * sum_d Q[d,q]*Q[d,k]
// Q slab [64][512]. Tile 128q x 128k, reduction d=64 in 4 chunks of 16.
// grid = (4 ktile, 4 qtile, 128 heads), block 256.
// ---------------------------------------------------------------------------
__global__ __launch_bounds__(256)
void scores_mma_kernel(const float* __restrict__ Qg, float* __restrict__ S)
{
    const int ch = blockIdx.z;
    const float* Q = Qg + (size_t)((ch >> 4) * FF + (ch & 15) * DD) * WW;
    const int q0 = blockIdx.y * 128;
    const int k0 = blockIdx.x * 128;

    __shared__ float As[16][132];   // [d][q]
    __shared__ float Bs[16][132];   // [d][k]

    const int tid  = threadIdx.x;
    const int lane = tid & 31;
    const int wid  = tid >> 5;
    const int wm   = (wid >> 2) * 64;
    const int wn   = (wid & 3) * 32;
    const int lg   = lane >> 2;
    const int lt   = lane & 3;

    const int kr = tid >> 4;          // 0..15 (d row)
    const int mc = (tid & 15) * 8;    // col base (8 floats)

    float acc[4][4][4];
    #pragma unroll
    for (int mi = 0; mi < 4; ++mi)
        #pragma unroll
        for (int ni = 0; ni < 4; ++ni)
            #pragma unroll
            for (int r = 0; r < 4; ++r) acc[mi][ni][r] = 0.f;

    for (int d0 = 0; d0 < DD; d0 += 16) {
        const float* Qr = Q + (size_t)(d0 + kr) * WW;
        float4 qa = *(const float4*)(Qr + q0 + mc);
        float4 qb = *(const float4*)(Qr + q0 + mc + 4);
        float4 ka = *(const float4*)(Qr + k0 + mc);
        float4 kb4 = *(const float4*)(Qr + k0 + mc + 4);
        As[kr][mc + 0] = to_tf32(qa.x); As[kr][mc + 1] = to_tf32(qa.y);
        As[kr][mc + 2] = to_tf32(qa.z); As[kr][mc + 3] = to_tf32(qa.w);
        As[kr][mc + 4] = to_tf32(qb.x); As[kr][mc + 5] = to_tf32(qb.y);
        As[kr][mc + 6] = to_tf32(qb.z); As[kr][mc + 7] = to_tf32(qb.w);
        Bs[kr][mc + 0] = to_tf32(ka.x); Bs[kr][mc + 1] = to_tf32(ka.y);
        Bs[kr][mc + 2] = to_tf32(ka.z); Bs[kr][mc + 3] = to_tf32(ka.w);
        Bs[kr][mc + 4] = to_tf32(kb4.x); Bs[kr][mc + 5] = to_tf32(kb4.y);
        Bs[kr][mc + 6] = to_tf32(kb4.z); Bs[kr][mc + 7] = to_tf32(kb4.w);
        __syncthreads();

        #pragma unroll
        for (int ks = 0; ks < 2; ++ks) {
            const int kbb = ks * 8 + lt;
            uint32_t a[4][4];
            #pragma unroll
            for (int mi = 0; mi < 4; ++mi) {
                const int m = wm + mi * 16 + lg;
                a[mi][0] = __float_as_uint(As[kbb][m]);
                a[mi][1] = __float_as_uint(As[kbb][m + 8]);
                a[mi][2] = __float_as_uint(As[kbb + 4][m]);
                a[mi][3] = __float_as_uint(As[kbb + 4][m + 8]);
            }
            uint32_t bf[4][2];
            #pragma unroll
            for (int ni = 0; ni < 4; ++ni) {
                const int n = wn + ni * 8 + lg;
                bf[ni][0] = __float_as_uint(Bs[kbb][n]);
                bf[ni][1] = __float_as_uint(Bs[kbb + 4][n]);
            }
            #pragma unroll
            for (int mi = 0; mi < 4; ++mi)
                #pragma unroll
                for (int ni = 0; ni < 4; ++ni)
                    MMA_TF32(acc[mi][ni], a[mi], bf[ni]);
        }
        __syncthreads();
    }

    float* Sb = S + (size_t)ch * WW * WW;
    const float scale = 1.0f / 32.0f;
    #pragma unroll
    for (int mi = 0; mi < 4; ++mi) {
        const int r0 = q0 + wm + mi * 16 + lg;
        #pragma unroll
        for (int ni = 0; ni < 4; ++ni) {
            const int cc = k0 + wn + ni * 8 + lt * 2;
            #pragma unroll
            for (int half = 0; half < 2; ++half) {
                const size_t idx = (size_t)(r0 + half * 8) * WW + cc;
                *(float2*)(Sb + idx) = make_float2(
                    acc[mi][ni][half * 2 + 0] * scale,
                    acc[mi][ni][half * 2 + 1] * scale);
            }
        }
    }
}

// ---------------------------------------------------------------------------
// Row softmax over 512 elements; one warp per row.
// ---------------------------------------------------------------------------
__global__ void softmax_kernel(float* __restrict__ S)
{
    const int row  = blockIdx.x * 8 + (threadIdx.x >> 5);
    const int lane = threadIdx.x & 31;
    float* Sr = S + (size_t)row * WW;

    float v[16];
    float mx = -1e30f;
    #pragma unroll
    for (int i = 0; i < 16; ++i) {
        v[i] = Sr[lane + i * 32];
        mx = fmaxf(mx, v[i]);
    }
    #pragma unroll
    for (int o = 16; o > 0; o >>= 1) mx = fmaxf(mx, __shfl_xor_sync(0xFFFFFFFFu, mx, o));
    float sum = 0.f;
    #pragma unroll
    for (int i = 0; i < 16; ++i) {
        v[i] = expf(v[i] - mx);
        sum += v[i];
    }
    #pragma unroll
    for (int o = 16; o > 0; o >>= 1) sum += __shfl_xor_sync(0xFFFFFFFFu, sum, o);
    const float inv = 1.0f / sum;
    #pragma unroll
    for (int i = 0; i < 16; ++i) Sr[lane + i * 32] = v[i] * inv;
}

// ---------------------------------------------------------------------------
// AV (tensor core): per head, O'[q,d] = sum_k P[q,k] * V[d,k];
// written transposed into slab layout O[d][q].
// A = probs [512][512] row-major; B = V slab [64][512] (transposed in smem).
// Tile 128q x 64d, KB=16. grid = (4 qtiles, 128 heads), block 256.
// ---------------------------------------------------------------------------
__global__ __launch_bounds__(256)
void av_mma_kernel(const float* __restrict__ S, const float* __restrict__ Vg,
                   float* __restrict__ Og)
{
    const int ch = blockIdx.y;
    const size_t hoff = (size_t)((ch >> 4) * FF + (ch & 15) * DD) * WW;
    const float* V = Vg + hoff;                 // [64][512]
    float*       O = Og + hoff;                 // [64][512]
    const float* A = S + (size_t)ch * WW * WW;  // [512][512]
    const int q0 = blockIdx.x * 128;

    __shared__ float As[16][132];   // [k][q]
    __shared__ float Bs[16][68];    // [k][d]

    const int tid  = threadIdx.x;
    const int lane = tid & 31;
    const int wid  = tid >> 5;
    const int wm   = (wid >> 2) * 64;     // q offset
    const int wn   = (wid & 3) * 16;      // d offset
    const int lg   = lane >> 2;
    const int lt   = lane & 3;

    const int qr = tid >> 1;              // 0..127
    const int qc = (tid & 1) * 8;         // k base (A load)
    const int dr = tid >> 2;              // 0..63
    const int dc = (tid & 3) * 4;         // k base (V load)

    float acc[4][2][4];
    #pragma unroll
    for (int mi = 0; mi < 4; ++mi)
        #pragma unroll
        for (int ni = 0; ni < 2; ++ni)
            #pragma unroll
            for (int r = 0; r < 4; ++r) acc[mi][ni][r] = 0.f;

    const float* Aq = A + (size_t)(q0 + qr) * WW;
    const float* Vd = V + (size_t)dr * WW;

    float4 pa0 = *(const float4*)(Aq + qc);
    float4 pa1 = *(const float4*)(Aq + qc + 4);
    float4 pv  = *(const float4*)(Vd + dc);

    for (int k0 = 0; k0 < WW; k0 += 16) {
        As[qc + 0][qr] = to_tf32(pa0.x);
        As[qc + 1][qr] = to_tf32(pa0.y);
        As[qc + 2][qr] = to_tf32(pa0.z);
        As[qc + 3][qr] = to_tf32(pa0.w);
        As[qc + 4][qr] = to_tf32(pa1.x);
        As[qc + 5][qr] = to_tf32(pa1.y);
        As[qc + 6][qr] = to_tf32(pa1.z);
        As[qc + 7][qr] = to_tf32(pa1.w);
        Bs[dc + 0][dr] = to_tf32(pv.x);
        Bs[dc + 1][dr] = to_tf32(pv.y);
        Bs[dc + 2][dr] = to_tf32(pv.z);
        Bs[dc + 3][dr] = to_tf32(pv.w);
        __syncthreads();

        if (k0 + 16 < WW) {
            pa0 = *(const float4*)(Aq + k0 + 16 + qc);
            pa1 = *(const float4*)(Aq + k0 + 20 + qc);
            pv  = *(const float4*)(Vd + k0 + 16 + dc);
        }

        #pragma unroll
        for (int ks = 0; ks < 2; ++ks) {
            const int kb = ks * 8 + lt;
            uint32_t a[4][4];
            #pragma unroll
            for (int mi = 0; mi < 4; ++mi) {
                const int m = wm + mi * 16 + lg;
                a[mi][0] = __float_as_uint(As[kb][m]);
                a[mi][1] = __float_as_uint(As[kb][m + 8]);
                a[mi][2] = __float_as_uint(As[kb + 4][m]);
                a[mi][3] = __float_as_uint(As[kb + 4][m + 8]);
            }
            uint32_t bf[2][2];
            #pragma unroll
            for (int ni = 0; ni < 2; ++ni) {
                const int n = wn + ni * 8 + lg;
                bf[ni][0] = __float_as_uint(Bs[kb][n]);
                bf[ni][1] = __float_as_uint(Bs[kb + 4][n]);
            }
            #pragma unroll
            for (int mi = 0; mi < 4; ++mi)
                #pragma unroll
                for (int ni = 0; ni < 2; ++ni)
                    MMA_TF32(acc[mi][ni], a[mi], bf[ni]);
        }
        __syncthreads();
    }

    // epilogue: O[d][q] = acc[q][d]
    #pragma unroll
    for (int mi = 0; mi < 4; ++mi) {
        const int r0 = q0 + wm + mi * 16 + lg;   // q index
        #pragma unroll
        for (int ni = 0; ni < 2; ++ni) {
            const int cc = wn + ni * 8 + lt * 2; // d index
            #pragma unroll
            for (int half = 0; half < 2; ++half) {
                const int qq = r0 + half * 8;
                O[(size_t)(cc + 0) * WW + qq] = acc[mi][ni][half * 2 + 0];
                O[(size_t)(cc + 1) * WW + qq] = acc[mi][ni][half * 2 + 1];
            }
        }
    }
}

// ---------------------------------------------------------------------------
// Launch
// ---------------------------------------------------------------------------
extern "C" void kernel_launch(void* const* d_in, const int* in_sizes, int n_in,
                              void* d_out, int out_size)
{
    const float* x   = (const float*)d_in[0];
    const float* n1g = (const float*)d_in[1];
    const float* n1b = (const float*)d_in[2];
    const float* wq  = (const float*)d_in[3];
    const float* wo  = (const float*)d_in[4];
    const float* rf  = (const float*)d_in[5];
    const float* n2g = (const float*)d_in[6];
    const float* n2b = (const float*)d_in[7];
    const float* w1  = (const float*)d_in[8];
    const float* w2  = (const float*)d_in[9];
    float* out = (float*)d_out;

    float *z, *p, *q, *s, *o, *h;
    cudaGetSymbolAddress((void**)&z, g_z);
    cudaGetSymbolAddress((void**)&p, g_p);
    cudaGetSymbolAddress((void**)&q, g_q);
    cudaGetSymbolAddress((void**)&s, g_s);
    cudaGetSymbolAddress((void**)&o, g_o);
    cudaGetSymbolAddress((void**)&h, g_h);

    dim3 lnBlock(32, 8), lnGrid(WW / 32, CC);

    // 1. z = LN1(x)
    ln_kernel<<<lnGrid, lnBlock>>>(x, n1g, n1b, z);
    // 2. p = Wq @ z
    tgemm_kernel<0><<<dim3(4, 8, CC), 256>>>(wq, z, p, nullptr, FF, FF);
    // 3. q = rope(p)
    rope_kernel<<<NELEM / 256, 256>>>(p, rf, q);
    // 4. scores (tensor core)
    scores_mma_kernel<<<dim3(4, 4, CC * HH), 256>>>(q, s);
    // 5. softmax
    softmax_kernel<<<CC * HH * WW / 8, 256>>>(s);
    // 6. o = A @ V (tensor core), V = p
    av_mma_kernel<<<dim3(4, CC * HH), 256>>>(s, p, o);
    // 7. out = x + Wo @ o
    tgemm_kernel<1><<<dim3(4, 8, CC), 256>>>(wo, o, out, x, FF, FF);
    // 8. z = LN2(out)
    ln_kernel<<<lnGrid, lnBlock>>>(out, n2g, n2b, z);
    // 9. h = gelu(W1 @ z)
    tgemm_kernel<2><<<dim3(4, FHID / 128, CC), 256>>>(w1, z, h, nullptr, FHID, FF);
    // 10. out += W2 @ h
    tgemm_kernel<3><<<dim3(4, 8, CC), 256>>>(w2, h, out, nullptr, FF, FHID);
}

// round 4
// speedup vs baseline: 2.9608x; 1.3640x over previous
#include <cuda_runtime.h>
#include <math.h>
#include <stdint.h>

// ---------------------------------------------------------------------------
// FrameTransformer: B=1, C=8, F=1024, W=512, H=16, D=64, EXP=4
// Round 4: cp.async double-buffered tf32 tensor-core GEMMs (raw-bit tf32).
// ---------------------------------------------------------------------------

#define CC 8
#define FF 1024
#define WW 512
#define HH 16
#define DD 64
#define EXPAND 4
#define FHID (FF * EXPAND)   // 4096
#define NELEM (CC * FF * WW) // 4,194,304

// Scratch (device globals; no runtime allocation allowed)
__device__ float g_z[NELEM];                 // LN output
__device__ float g_p[NELEM];                 // P = Wq @ z  (also V)
__device__ float g_q[NELEM];                 // RoPE(P) (q == k)
__device__ float g_s[CC * HH * WW * WW];     // attention scores / probs (134 MB)
__device__ float g_o[NELEM];                 // attention output (pre-Wo)
__device__ float g_h[CC * FHID * WW];        // MLP hidden (67 MB)

#define MMA_TF32(C, A, B)                                                     \
    asm volatile(                                                             \
        "mma.sync.aligned.m16n8k8.row.col.f32.tf32.tf32.f32 "                 \
        "{%0,%1,%2,%3}, {%4,%5,%6,%7}, {%8,%9}, {%0,%1,%2,%3};"               \
        : "+f"((C)[0]), "+f"((C)[1]), "+f"((C)[2]), "+f"((C)[3])              \
        : "r"((A)[0]), "r"((A)[1]), "r"((A)[2]), "r"((A)[3]),                 \
          "r"((B)[0]), "r"((B)[1]))

__device__ __forceinline__ void cp16(uint32_t dst, const void* src) {
    asm volatile("cp.async.cg.shared.global [%0], [%1], 16;" :: "r"(dst), "l"(src));
}
#define CP_COMMIT() asm volatile("cp.async.commit_group;")

// ---------------------------------------------------------------------------
// Frame norm over F for each (c, w) column. x layout: [C][F][W]
// ---------------------------------------------------------------------------
__global__ void ln_kernel(const float* __restrict__ x,
                          const float* __restrict__ g,
                          const float* __restrict__ b,
                          float* __restrict__ z)
{
    const int c  = blockIdx.y;
    const int w  = blockIdx.x * 32 + threadIdx.x;
    const int ty = threadIdx.y;
    const float* xc = x + (size_t)c * FF * WW;
    float*       zc = z + (size_t)c * FF * WW;

    float sum = 0.f, sq = 0.f;
    for (int f = ty; f < FF; f += 8) {
        float v = xc[(size_t)f * WW + w];
        sum += v;
        sq  = fmaf(v, v, sq);
    }
    __shared__ float s_sum[8][32];
    __shared__ float s_sq[8][32];
    s_sum[ty][threadIdx.x] = sum;
    s_sq[ty][threadIdx.x]  = sq;
    __syncthreads();
    if (ty == 0) {
        #pragma unroll
        for (int i = 1; i < 8; ++i) {
            sum += s_sum[i][threadIdx.x];
            sq  += s_sq[i][threadIdx.x];
        }
        float mu  = sum * (1.0f / FF);
        float var = sq * (1.0f / FF) - mu * mu;
        s_sum[0][threadIdx.x] = mu;
        s_sq[0][threadIdx.x]  = rsqrtf(var + 1e-5f);
    }
    __syncthreads();
    const float mu   = s_sum[0][threadIdx.x];
    const float rinv = s_sq[0][threadIdx.x];
    for (int f = ty; f < FF; f += 8) {
        float v = xc[(size_t)f * WW + w];
        zc[(size_t)f * WW + w] = (v - mu) * rinv * g[f] + b[f];
    }
}

// ---------------------------------------------------------------------------
// Tensor-core batched GEMM: Out[c] = W[c] (MxK row-major) @ In[c] (Kx512 rm)
// MODE 0: store; 1: store + Res; 2: store gelu(acc); 3: Out += acc
// 256 thr (8 warps), tile 128x128, warp 64x32, BK=16, tf32 mma (raw fp32 bits),
// 2-stage cp.async double buffering, conflict-free smem layouts.
// ---------------------------------------------------------------------------
template <int MODE>
__global__ __launch_bounds__(256)
void tgemm_kernel(const float* __restrict__ Wt, const float* __restrict__ In,
                  float* __restrict__ Out, const float* __restrict__ Res,
                  int M, int K)
{
    const int c = blockIdx.z;
    Wt  += (size_t)c * M * K;
    In  += (size_t)c * K * WW;
    Out += (size_t)c * M * WW;
    if (MODE == 1) Res += (size_t)c * M * WW;

    __shared__ float As[2][128][20];   // [stage][m][k], pad 16->20
    __shared__ float Bs[2][16][136];   // [stage][k][n], pad 128->136

    const int tid  = threadIdx.x;
    const int lane = tid & 31;
    const int wid  = tid >> 5;
    const int m0   = blockIdx.y * 128;
    const int n0   = blockIdx.x * 128;
    const int wm   = (wid >> 2) * 64;
    const int wn   = (wid & 3) * 32;
    const int lg   = lane >> 2;
    const int lt   = lane & 3;

    // cp.async chunk mapping (two 16B chunks per thread per operand)
    const int a_row = tid >> 2;            // 0..63  (+64 for second chunk)
    const int a_kc  = (tid & 3) * 4;       // 0/4/8/12
    const int b_row = tid >> 5;            // 0..7   (+8 for second chunk)
    const int b_nc  = (tid & 31) * 4;      // 0..124

    const float* Apg = Wt + (size_t)(m0 + a_row) * K + a_kc;
    const float* Bpg = In + n0 + b_nc;

    const int KT = K >> 4;

    // stage 0 prefetch
    {
        cp16(__cvta_generic_to_shared(&As[0][a_row][a_kc]),      Apg);
        cp16(__cvta_generic_to_shared(&As[0][a_row + 64][a_kc]), Apg + (size_t)64 * K);
        cp16(__cvta_generic_to_shared(&Bs[0][b_row][b_nc]),      Bpg + (size_t)b_row * WW);
        cp16(__cvta_generic_to_shared(&Bs[0][b_row + 8][b_nc]),  Bpg + (size_t)(b_row + 8) * WW);
        CP_COMMIT();
    }

    float acc[4][4][4];
    #pragma unroll
    for (int mi = 0; mi < 4; ++mi)
        #pragma unroll
        for (int ni = 0; ni < 4; ++ni)
            #pragma unroll
            for (int r = 0; r < 4; ++r) acc[mi][ni][r] = 0.f;

    for (int kt = 0; kt < KT; ++kt) {
        if (kt + 1 < KT) {
            const int s  = (kt + 1) & 1;
            const int k0 = (kt + 1) << 4;
            cp16(__cvta_generic_to_shared(&As[s][a_row][a_kc]),      Apg + k0);
            cp16(__cvta_generic_to_shared(&As[s][a_row + 64][a_kc]), Apg + (size_t)64 * K + k0);
            cp16(__cvta_generic_to_shared(&Bs[s][b_row][b_nc]),      Bpg + (size_t)(k0 + b_row) * WW);
            cp16(__cvta_generic_to_shared(&Bs[s][b_row + 8][b_nc]),  Bpg + (size_t)(k0 + b_row + 8) * WW);
            CP_COMMIT();
            asm volatile("cp.async.wait_group 1;");
        } else {
            asm volatile("cp.async.wait_group 0;");
        }
        __syncthreads();

        const int buf = kt & 1;
        #pragma unroll
        for (int ks = 0; ks < 2; ++ks) {
            const int kb = ks * 8 + lt;
            uint32_t a[4][4];
            #pragma unroll
            for (int mi = 0; mi < 4; ++mi) {
                const int m = wm + mi * 16 + lg;
                a[mi][0] = __float_as_uint(As[buf][m][kb]);
                a[mi][1] = __float_as_uint(As[buf][m + 8][kb]);
                a[mi][2] = __float_as_uint(As[buf][m][kb + 4]);
                a[mi][3] = __float_as_uint(As[buf][m + 8][kb + 4]);
            }
            uint32_t bfr[4][2];
            #pragma unroll
            for (int ni = 0; ni < 4; ++ni) {
                const int n = wn + ni * 8 + lg;
                bfr[ni][0] = __float_as_uint(Bs[buf][kb][n]);
                bfr[ni][1] = __float_as_uint(Bs[buf][kb + 4][n]);
            }
            #pragma unroll
            for (int mi = 0; mi < 4; ++mi)
                #pragma unroll
                for (int ni = 0; ni < 4; ++ni)
                    MMA_TF32(acc[mi][ni], a[mi], bfr[ni]);
        }
        __syncthreads();
    }

    // epilogue
    #pragma unroll
    for (int mi = 0; mi < 4; ++mi) {
        const int r0 = m0 + wm + mi * 16 + lg;
        #pragma unroll
        for (int ni = 0; ni < 4; ++ni) {
            const int cc = n0 + wn + ni * 8 + lt * 2;
            #pragma unroll
            for (int half = 0; half < 2; ++half) {
                const int row = r0 + half * 8;
                const size_t idx = (size_t)row * WW + cc;
                float v0 = acc[mi][ni][half * 2 + 0];
                float v1 = acc[mi][ni][half * 2 + 1];
                if (MODE == 1) {
                    float2 rv = *(const float2*)(Res + idx);
                    v0 += rv.x; v1 += rv.y;
                } else if (MODE == 2) {
                    v0 = 0.5f * v0 * (1.0f + erff(v0 * 0.70710678118654752f));
                    v1 = 0.5f * v1 * (1.0f + erff(v1 * 0.70710678118654752f));
                } else if (MODE == 3) {
                    float2 rv = *(const float2*)(Out + idx);
                    v0 += rv.x; v1 += rv.y;
                }
                *(float2*)(Out + idx) = make_float2(v0, v1);
            }
        }
    }
}

// ---------------------------------------------------------------------------
// RoPE: q[c, h*64+d, w]. First 32 dims of each head rotated (interleaved).
// ---------------------------------------------------------------------------
__global__ void rope_kernel(const float* __restrict__ p,
                            const float* __restrict__ freqs,
                            float* __restrict__ q)
{
    int n = blockIdx.x * blockDim.x + threadIdx.x;
    if (n >= NELEM) return;
    const int w = n & (WW - 1);
    const int f = (n >> 9) & (FF - 1);
    const int d = f & (DD - 1);
    float v = p[n];
    if (d >= 32) { q[n] = v; return; }
    const int j = d >> 1;
    const float ang = (float)w * freqs[j];
    const float cs = cosf(ang);
    const float sn = sinf(ang);
    if ((d & 1) == 0) {
        float v2 = p[n + WW];
        q[n] = v * cs - v2 * sn;
    } else {
        float v2 = p[n - WW];
        q[n] = v * cs + v2 * sn;
    }
}

// ---------------------------------------------------------------------------
// Scores (tensor core): per (c,h): S[q,k] = (1/32) * sum_d Q[d,q]*Q[d,k]
// Q slab [64][512]. Tile 128q x 128k. grid = (4, 4, 128), block 256.
// ---------------------------------------------------------------------------
__global__ __launch_bounds__(256)
void scores_mma_kernel(const float* __restrict__ Qg, float* __restrict__ S)
{
    const int ch = blockIdx.z;
    const float* Q = Qg + (size_t)((ch >> 4) * FF + (ch & 15) * DD) * WW;
    const int q0 = blockIdx.y * 128;
    const int k0 = blockIdx.x * 128;

    __shared__ float As[16][132];   // [d][q]
    __shared__ float Bs[16][132];   // [d][k]

    const int tid  = threadIdx.x;
    const int lane = tid & 31;
    const int wid  = tid >> 5;
    const int wm   = (wid >> 2) * 64;
    const int wn   = (wid & 3) * 32;
    const int lg   = lane >> 2;
    const int lt   = lane & 3;

    const int kr = tid >> 4;          // 0..15 (d row)
    const int mc = (tid & 15) * 8;    // col base (8 floats)

    float acc[4][4][4];
    #pragma unroll
    for (int mi = 0; mi < 4; ++mi)
        #pragma unroll
        for (int ni = 0; ni < 4; ++ni)
            #pragma unroll
            for (int r = 0; r < 4; ++r) acc[mi][ni][r] = 0.f;

    for (int d0 = 0; d0 < DD; d0 += 16) {
        const float* Qr = Q + (size_t)(d0 + kr) * WW;
        float4 qa = *(const float4*)(Qr + q0 + mc);
        float4 qb = *(const float4*)(Qr + q0 + mc + 4);
        float4 ka = *(const float4*)(Qr + k0 + mc);
        float4 kb4 = *(const float4*)(Qr + k0 + mc + 4);
        *(float4*)&As[kr][mc]     = qa;
        *(float4*)&As[kr][mc + 4] = qb;
        *(float4*)&Bs[kr][mc]     = ka;
        *(float4*)&Bs[kr][mc + 4] = kb4;
        __syncthreads();

        #pragma unroll
        for (int ks = 0; ks < 2; ++ks) {
            const int kbb = ks * 8 + lt;
            uint32_t a[4][4];
            #pragma unroll
            for (int mi = 0; mi < 4; ++mi) {
                const int m = wm + mi * 16 + lg;
                a[mi][0] = __float_as_uint(As[kbb][m]);
                a[mi][1] = __float_as_uint(As[kbb][m + 8]);
                a[mi][2] = __float_as_uint(As[kbb + 4][m]);
                a[mi][3] = __float_as_uint(As[kbb + 4][m + 8]);
            }
            uint32_t bf[4][2];
            #pragma unroll
            for (int ni = 0; ni < 4; ++ni) {
                const int n = wn + ni * 8 + lg;
                bf[ni][0] = __float_as_uint(Bs[kbb][n]);
                bf[ni][1] = __float_as_uint(Bs[kbb + 4][n]);
            }
            #pragma unroll
            for (int mi = 0; mi < 4; ++mi)
                #pragma unroll
                for (int ni = 0; ni < 4; ++ni)
                    MMA_TF32(acc[mi][ni], a[mi], bf[ni]);
        }
        __syncthreads();
    }

    float* Sb = S + (size_t)ch * WW * WW;
    const float scale = 1.0f / 32.0f;
    #pragma unroll
    for (int mi = 0; mi < 4; ++mi) {
        const int r0 = q0 + wm + mi * 16 + lg;
        #pragma unroll
        for (int ni = 0; ni < 4; ++ni) {
            const int cc = k0 + wn + ni * 8 + lt * 2;
            #pragma unroll
            for (int half = 0; half < 2; ++half) {
                const size_t idx = (size_t)(r0 + half * 8) * WW + cc;
                *(float2*)(Sb + idx) = make_float2(
                    acc[mi][ni][half * 2 + 0] * scale,
                    acc[mi][ni][half * 2 + 1] * scale);
            }
        }
    }
}

// ---------------------------------------------------------------------------
// Row softmax over 512 elements; one warp per row.
// ---------------------------------------------------------------------------
__global__ void softmax_kernel(float* __restrict__ S)
{
    const int row  = blockIdx.x * 8 + (threadIdx.x >> 5);
    const int lane = threadIdx.x & 31;
    float* Sr = S + (size_t)row * WW;

    float v[16];
    float mx = -1e30f;
    #pragma unroll
    for (int i = 0; i < 16; ++i) {
        v[i] = Sr[lane + i * 32];
        mx = fmaxf(mx, v[i]);
    }
    #pragma unroll
    for (int o = 16; o > 0; o >>= 1) mx = fmaxf(mx, __shfl_xor_sync(0xFFFFFFFFu, mx, o));
    float sum = 0.f;
    #pragma unroll
    for (int i = 0; i < 16; ++i) {
        v[i] = expf(v[i] - mx);
        sum += v[i];
    }
    #pragma unroll
    for (int o = 16; o > 0; o >>= 1) sum += __shfl_xor_sync(0xFFFFFFFFu, sum, o);
    const float inv = 1.0f / sum;
    #pragma unroll
    for (int i = 0; i < 16; ++i) Sr[lane + i * 32] = v[i] * inv;
}

// ---------------------------------------------------------------------------
// AV (tensor core): per head, O'[q,d] = sum_k P[q,k] * V[d,k];
// written transposed into slab layout O[d][q].
// ---------------------------------------------------------------------------
__global__ __launch_bounds__(256)
void av_mma_kernel(const float* __restrict__ S, const float* __restrict__ Vg,
                   float* __restrict__ Og)
{
    const int ch = blockIdx.y;
    const size_t hoff = (size_t)((ch >> 4) * FF + (ch & 15) * DD) * WW;
    const float* V = Vg + hoff;                 // [64][512]
    float*       O = Og + hoff;                 // [64][512]
    const float* A = S + (size_t)ch * WW * WW;  // [512][512]
    const int q0 = blockIdx.x * 128;

    __shared__ float As[128][20];   // [q][k] chunk, pad 16->20
    __shared__ float Bs[16][68];    // [k][d]

    const int tid  = threadIdx.x;
    const int lane = tid & 31;
    const int wid  = tid >> 5;
    const int wm   = (wid >> 2) * 64;     // q offset
    const int wn   = (wid & 3) * 16;      // d offset
    const int lg   = lane >> 2;
    const int lt   = lane & 3;

    const int qr = tid >> 1;              // 0..127
    const int qc = (tid & 1) * 8;         // k base (A load)
    const int dr = tid >> 2;              // 0..63
    const int dc = (tid & 3) * 4;         // k base (V load)

    float acc[4][2][4];
    #pragma unroll
    for (int mi = 0; mi < 4; ++mi)
        #pragma unroll
        for (int ni = 0; ni < 2; ++ni)
            #pragma unroll
            for (int r = 0; r < 4; ++r) acc[mi][ni][r] = 0.f;

    const float* Aq = A + (size_t)(q0 + qr) * WW;
    const float* Vd = V + (size_t)dr * WW;

    for (int k0 = 0; k0 < WW; k0 += 16) {
        float4 pa0 = *(const float4*)(Aq + k0 + qc);
        float4 pa1 = *(const float4*)(Aq + k0 + qc + 4);
        float4 pv  = *(const float4*)(Vd + k0 + dc);
        *(float4*)&As[qr][qc]     = pa0;
        *(float4*)&As[qr][qc + 4] = pa1;
        Bs[dc + 0][dr] = pv.x;
        Bs[dc + 1][dr] = pv.y;
        Bs[dc + 2][dr] = pv.z;
        Bs[dc + 3][dr] = pv.w;
        __syncthreads();

        #pragma unroll
        for (int ks = 0; ks < 2; ++ks) {
            const int kb = ks * 8 + lt;
            uint32_t a[4][4];
            #pragma unroll
            for (int mi = 0; mi < 4; ++mi) {
                const int m = wm + mi * 16 + lg;
                a[mi][0] = __float_as_uint(As[m][kb]);
                a[mi][1] = __float_as_uint(As[m + 8][kb]);
                a[mi][2] = __float_as_uint(As[m][kb + 4]);
                a[mi][3] = __float_as_uint(As[m + 8][kb + 4]);
            }
            uint32_t bf[2][2];
            #pragma unroll
            for (int ni = 0; ni < 2; ++ni) {
                const int n = wn + ni * 8 + lg;
                bf[ni][0] = __float_as_uint(Bs[kb][n]);
                bf[ni][1] = __float_as_uint(Bs[kb + 4][n]);
            }
            #pragma unroll
            for (int mi = 0; mi < 4; ++mi)
                #pragma unroll
                for (int ni = 0; ni < 2; ++ni)
                    MMA_TF32(acc[mi][ni], a[mi], bf[ni]);
        }
        __syncthreads();
    }

    // epilogue: O[d][q] = acc[q][d]
    #pragma unroll
    for (int mi = 0; mi < 4; ++mi) {
        const int r0 = q0 + wm + mi * 16 + lg;   // q index
        #pragma unroll
        for (int ni = 0; ni < 2; ++ni) {
            const int cc = wn + ni * 8 + lt * 2; // d index
            #pragma unroll
            for (int half = 0; half < 2; ++half) {
                const int qq = r0 + half * 8;
                O[(size_t)(cc + 0) * WW + qq] = acc[mi][ni][half * 2 + 0];
                O[(size_t)(cc + 1) * WW + qq] = acc[mi][ni][half * 2 + 1];
            }
        }
    }
}

// ---------------------------------------------------------------------------
// Launch
// ---------------------------------------------------------------------------
extern "C" void kernel_launch(void* const* d_in, const int* in_sizes, int n_in,
                              void* d_out, int out_size)
{
    const float* x   = (const float*)d_in[0];
    const float* n1g = (const float*)d_in[1];
    const float* n1b = (const float*)d_in[2];
    const float* wq  = (const float*)d_in[3];
    const float* wo  = (const float*)d_in[4];
    const float* rf  = (const float*)d_in[5];
    const float* n2g = (const float*)d_in[6];
    const float* n2b = (const float*)d_in[7];
    const float* w1  = (const float*)d_in[8];
    const float* w2  = (const float*)d_in[9];
    float* out = (float*)d_out;

    float *z, *p, *q, *s, *o, *h;
    cudaGetSymbolAddress((void**)&z, g_z);
    cudaGetSymbolAddress((void**)&p, g_p);
    cudaGetSymbolAddress((void**)&q, g_q);
    cudaGetSymbolAddress((void**)&s, g_s);
    cudaGetSymbolAddress((void**)&o, g_o);
    cudaGetSymbolAddress((void**)&h, g_h);

    dim3 lnBlock(32, 8), lnGrid(WW / 32, CC);

    // 1. z = LN1(x)
    ln_kernel<<<lnGrid, lnBlock>>>(x, n1g, n1b, z);
    // 2. p = Wq @ z
    tgemm_kernel<0><<<dim3(4, 8, CC), 256>>>(wq, z, p, nullptr, FF, FF);
    // 3. q = rope(p)
    rope_kernel<<<NELEM / 256, 256>>>(p, rf, q);
    // 4. scores (tensor core)
    scores_mma_kernel<<<dim3(4, 4, CC * HH), 256>>>(q, s);
    // 5. softmax
    softmax_kernel<<<CC * HH * WW / 8, 256>>>(s);
    // 6. o = A @ V (tensor core), V = p
    av_mma_kernel<<<dim3(4, CC * HH), 256>>>(s, p, o);
    // 7. out = x + Wo @ o
    tgemm_kernel<1><<<dim3(4, 8, CC), 256>>>(wo, o, out, x, FF, FF);
    // 8. z = LN2(out)
    ln_kernel<<<lnGrid, lnBlock>>>(out, n2g, n2b, z);
    // 9. h = gelu(W1 @ z)
    tgemm_kernel<2><<<dim3(4, FHID / 128, CC), 256>>>(w1, z, h, nullptr, FHID, FF);
    // 10. out += W2 @ h
    tgemm_kernel<3><<<dim3(4, 8, CC), 256>>>(w2, h, out, nullptr, FF, FHID);
}